// round 4
// baseline (speedup 1.0000x reference)
#include <cuda_runtime.h>
#include <math_constants.h>

#define N_PTS 16384
#define C_DIM 64
#define K_NN  16
#define NSPLIT 4
#define SLICE (N_PTS / NSPLIT)   // 4096
#define NT 128                    // threads per knn block
#define BQ 256                    // queries per knn block (2 per thread)
#define TN 128                    // db points per smem tile

// Scratch (device globals; no dynamic allocation allowed)
__device__ float g_sq[N_PTS];
__device__ float g_pd[NSPLIT * N_PTS * K_NN];   // partial top-k distances
__device__ int   g_pi[NSPLIT * N_PTS * K_NN];   // partial top-k indices
__device__ int   g_knn[N_PTS * K_NN];           // final knn indices
__device__ float g_A[N_PTS * 256];              // x@(W1-W2)+b
__device__ float g_B[N_PTS * 256];              // x@W2

// ---------------- packed f32x2 helpers ----------------
__device__ __forceinline__ unsigned long long ffma2(unsigned long long a,
                                                    unsigned long long b,
                                                    unsigned long long c) {
    unsigned long long d;
    asm("fma.rn.f32x2 %0, %1, %2, %3;" : "=l"(d) : "l"(a), "l"(b), "l"(c));
    return d;
}
__device__ __forceinline__ unsigned long long pack2(float lo, float hi) {
    unsigned long long p;
    asm("mov.b64 %0, {%1, %2};" : "=l"(p) : "f"(lo), "f"(hi));
    return p;
}
__device__ __forceinline__ float sum2(unsigned long long p) {
    float lo, hi;
    asm("mov.b64 {%0, %1}, %2;" : "=f"(lo), "=f"(hi) : "l"(p));
    return lo + hi;
}

// register insertion into sorted top-k (cold path; guard d < kd[15] outside)
__device__ __forceinline__ void insert16(float d, int i,
                                         float (&kd)[K_NN], int (&ki)[K_NN]) {
    kd[K_NN - 1] = d; ki[K_NN - 1] = i;
#pragma unroll
    for (int t = K_NN - 1; t > 0; --t) {
        if (kd[t] < kd[t - 1]) {
            float td = kd[t]; kd[t] = kd[t - 1]; kd[t - 1] = td;
            int ti = ki[t]; ki[t] = ki[t - 1]; ki[t - 1] = ti;
        }
    }
}

// ---------------- 1) squared norms ----------------
__global__ void sqnorm_kernel(const float* __restrict__ x) {
    int i = blockIdx.x * blockDim.x + threadIdx.x;
    const float4* xr = (const float4*)(x + (long)i * C_DIM);
    float s = 0.f;
#pragma unroll
    for (int t = 0; t < C_DIM / 4; ++t) {
        float4 v = xr[t];
        s += v.x * v.x + v.y * v.y + v.z * v.z + v.w * v.w;
    }
    g_sq[i] = s;
}

// ---------------- 2) feature GEMMs: A = x@(W1-W2)+b, B = x@W2 ----------------
__global__ void feat_gemm_kernel(const float* __restrict__ x,
                                 const float* __restrict__ W,
                                 const float* __restrict__ b) {
    __shared__ float xs[16][C_DIM];
    int col = threadIdx.x;             // 0..255  (output column)
    int row0 = blockIdx.x * 16;
    ((float4*)xs)[col] = ((const float4*)(x + (long)row0 * C_DIM))[col];
    __syncthreads();

    float p1[16], p2[16];
#pragma unroll
    for (int r = 0; r < 16; ++r) { p1[r] = 0.f; p2[r] = 0.f; }

#pragma unroll 4
    for (int c = 0; c < C_DIM; ++c) {
        float w1 = __ldg(W + c * 256 + col);
        float w2 = __ldg(W + (C_DIM + c) * 256 + col);
#pragma unroll
        for (int r = 0; r < 16; ++r) {
            float xv = xs[r][c];
            p1[r] = fmaf(xv, w1, p1[r]);
            p2[r] = fmaf(xv, w2, p2[r]);
        }
    }
    float bias = __ldg(b + col);
#pragma unroll
    for (int r = 0; r < 16; ++r) {
        g_A[(long)(row0 + r) * 256 + col] = p1[r] - p2[r] + bias;
        g_B[(long)(row0 + r) * 256 + col] = p2[r];
    }
}

// ---------------- 3) KNN: 2 queries/thread, FFMA2, 4 acc chains ----------------
__global__ __launch_bounds__(NT, 2) void knn_part_kernel(const float* __restrict__ x) {
    __shared__ float db_s[TN * C_DIM];
    __shared__ float sq_s[TN];
    int tid = threadIdx.x;
    int q0 = blockIdx.x * BQ + tid;
    int q1 = q0 + NT;
    int s0 = blockIdx.y * SLICE;

    // query rows in registers, pre-scaled by -2 (exact: x2 scaling has no rounding)
    unsigned long long qa[C_DIM / 2], qb[C_DIM / 2];
    {
        const float2* xr0 = (const float2*)(x + (long)q0 * C_DIM);
        const float2* xr1 = (const float2*)(x + (long)q1 * C_DIM);
#pragma unroll
        for (int t = 0; t < C_DIM / 2; ++t) {
            float2 v0 = xr0[t];
            float2 v1 = xr1[t];
            qa[t] = pack2(-2.f * v0.x, -2.f * v0.y);
            qb[t] = pack2(-2.f * v1.x, -2.f * v1.y);
        }
    }
    float sqq0 = g_sq[q0];
    float sqq1 = g_sq[q1];

    float kd0[K_NN], kd1[K_NN];
    int   ki0[K_NN], ki1[K_NN];
#pragma unroll
    for (int t = 0; t < K_NN; ++t) {
        kd0[t] = CUDART_INF_F; ki0[t] = -1;
        kd1[t] = CUDART_INF_F; ki1[t] = -1;
    }
    float thr0 = CUDART_INF_F, thr1 = CUDART_INF_F;

    for (int tile = 0; tile < SLICE / TN; ++tile) {
        int base = s0 + tile * TN;
        __syncthreads();
#pragma unroll
        for (int it = 0; it < (TN * C_DIM / 4) / NT; ++it) {
            int off = it * NT + tid;
            ((float4*)db_s)[off] = ((const float4*)(x + (long)base * C_DIM))[off];
        }
        sq_s[tid] = g_sq[base + tid];
        __syncthreads();

        for (int j = 0; j < TN; ++j) {
            const float4* dbr = (const float4*)(db_s + j * C_DIM);
            unsigned long long a0 = 0ull, a1 = 0ull, b0 = 0ull, b1 = 0ull;
#pragma unroll
            for (int t = 0; t < C_DIM / 4; ++t) {
                float4 v = dbr[t];
                unsigned long long p0 = pack2(v.x, v.y);
                unsigned long long p1 = pack2(v.z, v.w);
                a0 = ffma2(qa[2 * t], p0, a0);
                a1 = ffma2(qa[2 * t + 1], p1, a1);
                b0 = ffma2(qb[2 * t], p0, b0);
                b1 = ffma2(qb[2 * t + 1], p1, b1);
            }
            float sqj = sq_s[j];
            int col = base + j;
            float d0 = sqq0 + sqj + sum2(a0) + sum2(a1);
            float d1 = sqq1 + sqj + sum2(b0) + sum2(b1);
            if (d0 < thr0 && col != q0) {
                insert16(d0, col, kd0, ki0);
                thr0 = kd0[K_NN - 1];
            }
            if (d1 < thr1 && col != q1) {
                insert16(d1, col, kd1, ki1);
                thr1 = kd1[K_NN - 1];
            }
        }
    }
    long ob0 = ((long)blockIdx.y * N_PTS + q0) * K_NN;
    long ob1 = ((long)blockIdx.y * N_PTS + q1) * K_NN;
#pragma unroll
    for (int t = 0; t < K_NN; ++t) {
        g_pd[ob0 + t] = kd0[t]; g_pi[ob0 + t] = ki0[t];
        g_pd[ob1 + t] = kd1[t]; g_pi[ob1 + t] = ki1[t];
    }
}

// ---------------- 4) merge split-K partial top-k lists ----------------
__global__ void merge_kernel() {
    int q = blockIdx.x * blockDim.x + threadIdx.x;
    float kd[K_NN];
    int   ki[K_NN];
#pragma unroll
    for (int t = 0; t < K_NN; ++t) { kd[t] = CUDART_INF_F; ki[t] = -1; }
    for (int s = 0; s < NSPLIT; ++s) {
        long ob = ((long)s * N_PTS + q) * K_NN;
#pragma unroll
        for (int t2 = 0; t2 < K_NN; ++t2) {
            float d = g_pd[ob + t2];
            int   i = g_pi[ob + t2];
            if (d < kd[K_NN - 1]) {
                insert16(d, i, kd, ki);
            }
        }
    }
#pragma unroll
    for (int t = 0; t < K_NN; ++t) g_knn[(long)q * K_NN + t] = ki[t];
}

// ---------------- 5) gather + max + relu + pixel-shuffle scatter ----------------
__global__ void gather_max_kernel(float* __restrict__ y) {
    int t = threadIdx.x;
    int q = blockIdx.x * 4 + (t >> 6);
    int c = t & 63;
    const int* idx = g_knn + (long)q * K_NN;
    const float4* Bv = (const float4*)g_B;
    float4 m = make_float4(-CUDART_INF_F, -CUDART_INF_F, -CUDART_INF_F, -CUDART_INF_F);
#pragma unroll
    for (int k = 0; k < K_NN; ++k) {
        int j = __ldg(idx + k);
        float4 bv = Bv[(long)j * 64 + c];
        m.x = fmaxf(m.x, bv.x); m.y = fmaxf(m.y, bv.y);
        m.z = fmaxf(m.z, bv.z); m.w = fmaxf(m.w, bv.w);
    }
    float4 a = ((const float4*)g_A)[(long)q * 64 + c];
    y[((long)q * 4 + 0) * 64 + c] = fmaxf(a.x + m.x, 0.f);
    y[((long)q * 4 + 1) * 64 + c] = fmaxf(a.y + m.y, 0.f);
    y[((long)q * 4 + 2) * 64 + c] = fmaxf(a.z + m.z, 0.f);
    y[((long)q * 4 + 3) * 64 + c] = fmaxf(a.w + m.w, 0.f);
}

extern "C" void kernel_launch(void* const* d_in, const int* in_sizes, int n_in,
                              void* d_out, int out_size) {
    const float* x = (const float*)d_in[0];   // (16384, 64) f32
    const float* W = (const float*)d_in[1];   // (128, 256) f32
    const float* b = (const float*)d_in[2];   // (256,) f32
    float* y = (float*)d_out;                 // (65536, 64) f32

    sqnorm_kernel<<<N_PTS / 256, 256>>>(x);
    feat_gemm_kernel<<<N_PTS / 16, 256>>>(x, W, b);
    knn_part_kernel<<<dim3(N_PTS / BQ, NSPLIT), NT>>>(x);
    merge_kernel<<<N_PTS / 64, 64>>>();
    gather_max_kernel<<<N_PTS / 4, 256>>>(y);
}